// round 3
// baseline (speedup 1.0000x reference)
#include <cuda_runtime.h>
#include <math.h>

#define Bn 4
#define Dn 64
#define Hn 64
#define Wn 64
#define CHn 150
#define PLANE 4096
#define VOL   262144
#define VOX   1048576

typedef unsigned long long ull;

__device__ float g_p[VOX];
__device__ float g_c[VOX];   // r * (1 - p)
__device__ float g_v[VOX];   // ping-pong buffer

// ---------------- packed f32x2 helpers (sm_103a) ----------------
__device__ __forceinline__ ull pk2(float a, float b) {
    ull r; asm("mov.b64 %0, {%1, %2};" : "=l"(r) : "f"(a), "f"(b)); return r;
}
__device__ __forceinline__ void upk2(ull v, float& a, float& b) {
    asm("mov.b64 {%0, %1}, %2;" : "=f"(a), "=f"(b) : "l"(v));
}
__device__ __forceinline__ ull fma2(ull a, ull b, ull c) {
    ull d; asm("fma.rn.f32x2 %0, %1, %2, %3;" : "=l"(d) : "l"(a), "l"(b), "l"(c));
    return d;
}
__device__ __forceinline__ float4 max4(float4 a, float4 b) {
    return make_float4(fmaxf(a.x, b.x), fmaxf(a.y, b.y),
                       fmaxf(a.z, b.z), fmaxf(a.w, b.w));
}
__device__ __forceinline__ float4 fma4(float4 p, float4 m, float4 c) {
    return make_float4(fmaf(p.x, m.x, c.x), fmaf(p.y, m.y, c.y),
                       fmaf(p.z, m.z, c.z), fmaf(p.w, m.w, c.w));
}

// ---------------------------------------------------------------------------
// Kernel 1: p = sigmoid(sum_c pw[c]*relu(conv3x3x3_c(x)+b[c]))
//           writes g_p, g_c = r*(1-p), and v0 = r into vout.
// Channel-paired FFMA2: weights (wA,wA,wB,wB) -> 1 LDS.128 feeds 4 fma2.
// ---------------------------------------------------------------------------
#define DCH 4
#define HT  16
#define XROW 68
#define XHL 18
#define XDL 6
#define NPAIR 75

__global__ __launch_bounds__(256) void compute_p_kernel(
    const float* __restrict__ image, const float* __restrict__ hw,
    const float* __restrict__ hb,    const float* __restrict__ pw,
    float* __restrict__ vout)
{
    __shared__ float  xs[XDL * XHL * XROW];   // 29376 B
    __shared__ float4 ws4[NPAIR * 28];        // (wA,wA,wB,wB) 33600 B
    __shared__ float4 bp4[NPAIR];             // (bA,bA,bB,bB)
    __shared__ float4 pp4[NPAIR];             // (pA,pA,pB,pB)

    const int tid = threadIdx.x;

    for (int i = tid; i < NPAIR * 27; i += 256) {
        const int pr = i / 27, t = i % 27;
        const float wA = hw[(pr * 2) * 27 + t];
        const float wB = hw[(pr * 2 + 1) * 27 + t];
        ws4[pr * 28 + t] = make_float4(wA, wA, wB, wB);
    }
    for (int i = tid; i < NPAIR; i += 256) {
        const float bA = hb[i * 2], bB = hb[i * 2 + 1];
        const float pA = pw[i * 2], pB = pw[i * 2 + 1];
        bp4[i] = make_float4(bA, bA, bB, bB);
        pp4[i] = make_float4(pA, pA, pB, pB);
    }

    const int d0 = blockIdx.x * DCH;
    const int h0 = blockIdx.y * HT;
    const int b  = blockIdx.z;
    const float* xg = image + (size_t)b * 2 * VOL;
    const float* rg = xg + VOL;

    for (int i = tid; i < XDL * XHL * 66; i += 256) {
        int wl = i % 66; int rest = i / 66;
        int hl = rest % XHL; int dl = rest / XHL;
        int gw = wl - 1, gh = h0 + hl - 1, gd = d0 + dl - 1;
        float v = 0.0f;
        if (gw >= 0 && gw < Wn && gh >= 0 && gh < Hn && gd >= 0 && gd < Dn)
            v = xg[((size_t)gd * Hn + gh) * Wn + gw];
        xs[(dl * XHL + hl) * XROW + wl] = v;
    }
    __syncthreads();

    const int wt = tid & 15;
    const int ht = tid >> 4;
    const int w0 = wt * 4;

    for (int dl = 0; dl < DCH; dl++) {
        ull P[9][5];
        #pragma unroll
        for (int r9 = 0; r9 < 9; r9++) {
            const int dz = r9 / 3, hy = r9 % 3;
            const float* base = &xs[((dl + dz) * XHL + (ht + hy)) * XROW + w0];
            float4 a  = *(const float4*)base;
            float2 b2 = *(const float2*)(base + 4);
            P[r9][0] = pk2(a.x, a.y);
            P[r9][1] = pk2(a.y, a.z);
            P[r9][2] = pk2(a.z, a.w);
            P[r9][3] = pk2(a.w, b2.x);
            P[r9][4] = pk2(b2.x, b2.y);
        }

        ull z01 = 0ull, z23 = 0ull;

        #pragma unroll 1
        for (int cp = 0; cp < NPAIR; cp++) {
            const float4* wp = &ws4[cp * 28];
            const float4 bb = bp4[cp];
            ull aA01 = pk2(bb.x, bb.y), aA23 = aA01;
            ull aB01 = pk2(bb.z, bb.w), aB23 = aB01;
            #pragma unroll
            for (int t = 0; t < 27; t++) {
                const float4 w4 = wp[t];
                const ull lo = pk2(w4.x, w4.y);
                const ull hi = pk2(w4.z, w4.w);
                const int r9 = t / 3, kx = t % 3;
                aA01 = fma2(lo, P[r9][kx],     aA01);
                aA23 = fma2(lo, P[r9][kx + 2], aA23);
                aB01 = fma2(hi, P[r9][kx],     aB01);
                aB23 = fma2(hi, P[r9][kx + 2], aB23);
            }
            float a0, a1, a2, a3, b0, b1, b2, b3;
            upk2(aA01, a0, a1); upk2(aA23, a2, a3);
            upk2(aB01, b0, b1); upk2(aB23, b2, b3);
            a0 = fmaxf(a0, 0.f); a1 = fmaxf(a1, 0.f);
            a2 = fmaxf(a2, 0.f); a3 = fmaxf(a3, 0.f);
            b0 = fmaxf(b0, 0.f); b1 = fmaxf(b1, 0.f);
            b2 = fmaxf(b2, 0.f); b3 = fmaxf(b3, 0.f);
            const float4 pv = pp4[cp];
            const ull pA = pk2(pv.x, pv.y), pB = pk2(pv.z, pv.w);
            z01 = fma2(pA, pk2(a0, a1), z01);
            z23 = fma2(pA, pk2(a2, a3), z23);
            z01 = fma2(pB, pk2(b0, b1), z01);
            z23 = fma2(pB, pk2(b2, b3), z23);
        }

        float z0, z1, z2, z3;
        upk2(z01, z0, z1); upk2(z23, z2, z3);

        const int gd = d0 + dl, gh = h0 + ht;
        const size_t o = ((size_t)b * Dn + gd) * PLANE + gh * Wn + w0;
        const float4 r4 = *(const float4*)&rg[((size_t)gd * Hn + gh) * Wn + w0];

        const float p0 = 1.f / (1.f + __expf(-z0));
        const float p1 = 1.f / (1.f + __expf(-z1));
        const float p2 = 1.f / (1.f + __expf(-z2));
        const float p3 = 1.f / (1.f + __expf(-z3));

        *(float4*)&g_p[o]  = make_float4(p0, p1, p2, p3);
        *(float4*)&g_c[o]  = make_float4(r4.x * (1.f - p0), r4.y * (1.f - p1),
                                         r4.z * (1.f - p2), r4.w * (1.f - p3));
        *(float4*)&vout[o] = r4;
    }
}

// ---------------------------------------------------------------------------
// Kernel 2: TWO fused propagation iterations per launch.
// Block = 16-row slice of one (b,d) plane; loads 5 planes x 20 rows of v0,
// computes v1 on 3 planes x 18 rows (SMEM), then v2 on its slice.
// Clamped-index replication is exact for max-pooling (duplicates <= true
// value which is inside the window; p > 0 keeps the update monotone).
// ---------------------------------------------------------------------------
__global__ __launch_bounds__(256) void iter2_kernel(
    const float4* __restrict__ vin, float4* __restrict__ vout,
    const int* __restrict__ kptr, int it)
{
    __shared__ float4 s_v0[5][20][16];   // 25.6 KB
    __shared__ float4 s_dm[20][16];      // 5.1 KB (reused as d2max)
    __shared__ float4 s_hm[18][16];      // 4.6 KB (reused as hm2)
    __shared__ float4 s_v1[3][18][16];   // 13.8 KB

    const int blk = blockIdx.x;
    const int bd  = blk >> 2;
    const int b   = bd >> 6;
    const int d   = bd & 63;
    const int h0  = (blk & 3) * 16;
    const int tid = threadIdx.x;
    const int ks  = *kptr;

    const size_t bbase = (size_t)b * 64 * 1024;
    const float4* Gp = (const float4*)g_p;
    const float4* Gc = (const float4*)g_c;

    // Load v0: 5 planes (d-2..d+2) x 20 rows (h0-2..h0+17), clamped
    for (int i = tid; i < 5 * 20 * 16; i += 256) {
        const int c4 = i & 15; const int rest = i >> 4;
        const int row = rest % 20; const int pz = rest / 20;
        const int gd = min(63, max(0, d - 2 + pz));
        const int gh = min(63, max(0, h0 - 2 + row));
        s_v0[pz][row][c4] = vin[bbase + (size_t)gd * 1024 + gh * 16 + c4];
    }
    __syncthreads();

    // v1 on 3 planes
    for (int dz = 0; dz < 3; dz++) {
        // d-max over z for 20 rows
        for (int i = tid; i < 20 * 16; i += 256) {
            const int c4 = i & 15, row = i >> 4;
            s_dm[row][c4] = max4(max4(s_v0[dz][row][c4], s_v0[dz + 1][row][c4]),
                                 s_v0[dz + 2][row][c4]);
        }
        __syncthreads();
        // h-max for 18 rows
        for (int i = tid; i < 18 * 16; i += 256) {
            const int c4 = i & 15, rv = i >> 4;
            s_hm[rv][c4] = max4(max4(s_dm[rv][c4], s_dm[rv + 1][c4]),
                                s_dm[rv + 2][c4]);
        }
        __syncthreads();
        // w-max + update -> s_v1[dz]
        const int pd = min(63, max(0, d - 1 + dz));
        const size_t pbase = ((size_t)b * 64 + pd) * 1024;
        for (int i = tid; i < 18 * 16; i += 256) {
            const int c4 = i & 15, rv = i >> 4;
            const float* hmf = (const float*)&s_hm[rv][0];
            const int w0 = c4 * 4;
            const float4 hc = s_hm[rv][c4];
            const float lf = (c4 == 0)  ? hc.x : hmf[w0 - 1];
            const float rt = (c4 == 15) ? hc.w : hmf[w0 + 4];
            float4 m;
            m.x = fmaxf(lf,   fmaxf(hc.x, hc.y));
            m.y = fmaxf(hc.x, fmaxf(hc.y, hc.z));
            m.z = fmaxf(hc.y, fmaxf(hc.z, hc.w));
            m.w = fmaxf(hc.z, fmaxf(hc.w, rt));
            const int gh = min(63, max(0, h0 - 1 + rv));
            const size_t off = pbase + gh * 16 + c4;
            const float4 pp = Gp[off];
            const float4 cc = Gc[off];
            const float4 v0c = s_v0[dz + 1][rv + 1][c4];
            s_v1[dz][rv][c4] = max4(v0c, fma4(pp, m, cc));
        }
        __syncthreads();
    }

    // v2: d-max over v1 planes (18 rows)
    for (int i = tid; i < 18 * 16; i += 256) {
        const int c4 = i & 15, rv = i >> 4;
        s_dm[rv][c4] = max4(max4(s_v1[0][rv][c4], s_v1[1][rv][c4]),
                            s_v1[2][rv][c4]);
    }
    __syncthreads();
    // h-max for 16 output rows
    for (int i = tid; i < 16 * 16; i += 256) {
        const int c4 = i & 15, ro = i >> 4;
        s_hm[ro][c4] = max4(max4(s_dm[ro][c4], s_dm[ro + 1][c4]),
                            s_dm[ro + 2][c4]);
    }
    __syncthreads();
    // w-max + update + store
    {
        const int c4 = tid & 15, ro = tid >> 4;
        const float* hmf = (const float*)&s_hm[ro][0];
        const int w0 = c4 * 4;
        const float4 hc = s_hm[ro][c4];
        const float lf = (c4 == 0)  ? hc.x : hmf[w0 - 1];
        const float rt = (c4 == 15) ? hc.w : hmf[w0 + 4];
        float4 m;
        m.x = fmaxf(lf,   fmaxf(hc.x, hc.y));
        m.y = fmaxf(hc.x, fmaxf(hc.y, hc.z));
        m.z = fmaxf(hc.y, fmaxf(hc.z, hc.w));
        m.w = fmaxf(hc.z, fmaxf(hc.w, rt));
        const size_t off = bbase + (size_t)d * 1024 + (h0 + ro) * 16 + c4;
        const float4 pp = Gp[off];
        const float4 cc = Gc[off];
        const float4 v1c = s_v1[1][ro + 1][c4];
        float4 outv = max4(v1c, fma4(pp, m, cc));
        if (ks <= it)          outv = s_v0[2][ro + 2][c4];  // v0 center
        else if (ks == it + 1) outv = v1c;
        vout[off] = outv;
    }
}

// ---------------------------------------------------------------------------
extern "C" void kernel_launch(void* const* d_in, const int* in_sizes, int n_in,
                              void* d_out, int out_size)
{
    const float* image = (const float*)d_in[0];
    const float* hw    = (const float*)d_in[1];
    const float* hb    = (const float*)d_in[2];
    const float* pw    = (const float*)d_in[3];
    const int*   kptr  = (const int*)d_in[4];
    float* out = (float*)d_out;

    void* pv = nullptr;
    cudaGetSymbolAddress(&pv, g_v);
    float* vbuf = (float*)pv;

    // v0 -> g_v, so after 15 fused launches the final write lands in d_out
    compute_p_kernel<<<dim3(16, 4, 4), 256>>>(image, hw, hb, pw, vbuf);

    const float* src = vbuf;
    float* dst = out;
    for (int i = 0; i < 30; i += 2) {
        iter2_kernel<<<Bn * Dn * 4, 256>>>((const float4*)src, (float4*)dst, kptr, i);
        float* t = dst; dst = (float*)src; src = t;
    }
    // 15 launches: writes alternate out, g_v, ..., ending in d_out.
}

// round 4
// speedup vs baseline: 1.3882x; 1.3882x over previous
#include <cuda_runtime.h>
#include <math.h>

#define Bn 4
#define Dn 64
#define Hn 64
#define Wn 64
#define CHn 150
#define PLANE 4096
#define VOL   262144
#define VOX   1048576

typedef unsigned long long ull;

__device__ float g_p[VOX];
__device__ float g_c[VOX];   // r * (1 - p)
__device__ float g_v[VOX];   // ping-pong buffer

// ---------------- packed f32x2 helpers (sm_103a) ----------------
__device__ __forceinline__ ull pk2(float a, float b) {
    ull r; asm("mov.b64 %0, {%1, %2};" : "=l"(r) : "f"(a), "f"(b)); return r;
}
__device__ __forceinline__ void upk2(ull v, float& a, float& b) {
    asm("mov.b64 {%0, %1}, %2;" : "=f"(a), "=f"(b) : "l"(v));
}
__device__ __forceinline__ ull fma2(ull a, ull b, ull c) {
    ull d; asm("fma.rn.f32x2 %0, %1, %2, %3;" : "=l"(d) : "l"(a), "l"(b), "l"(c));
    return d;
}
__device__ __forceinline__ float4 max4(float4 a, float4 b) {
    return make_float4(fmaxf(a.x, b.x), fmaxf(a.y, b.y),
                       fmaxf(a.z, b.z), fmaxf(a.w, b.w));
}

// ---------------------------------------------------------------------------
// Kernel 1: p = sigmoid(sum_c pw[c]*relu(conv3x3x3_c(x)+b[c]))
//           writes g_p, g_c = r*(1-p), v0 = r into vout.
// Paired channels; weights (wA,wA,wB,wB): one LDS.128 = two ready ull pairs.
// At the FFMA2 rt=3 (RF banking) roofline ≈ 180 µs.
// ---------------------------------------------------------------------------
#define DCH 4
#define HT  16
#define XROW 68
#define XHL 18
#define XDL 6
#define NPAIR 75

__global__ __launch_bounds__(256) void compute_p_kernel(
    const float* __restrict__ image, const float* __restrict__ hw,
    const float* __restrict__ hb,    const float* __restrict__ pw,
    float* __restrict__ vout)
{
    __shared__ float  xs[XDL * XHL * XROW];   // 29376 B
    __shared__ float4 ws4[NPAIR * 28];        // (wA,wA,wB,wB) 33600 B
    __shared__ float4 bp4[NPAIR];             // (bA,bA,bB,bB)
    __shared__ float4 pp4[NPAIR];             // (pA,pA,pB,pB)

    const int tid = threadIdx.x;

    for (int i = tid; i < NPAIR * 27; i += 256) {
        const int pr = i / 27, t = i % 27;
        const float wA = hw[(pr * 2) * 27 + t];
        const float wB = hw[(pr * 2 + 1) * 27 + t];
        ws4[pr * 28 + t] = make_float4(wA, wA, wB, wB);
    }
    for (int i = tid; i < NPAIR; i += 256) {
        const float bA = hb[i * 2], bB = hb[i * 2 + 1];
        const float pA = pw[i * 2], pB = pw[i * 2 + 1];
        bp4[i] = make_float4(bA, bA, bB, bB);
        pp4[i] = make_float4(pA, pA, pB, pB);
    }

    const int d0 = blockIdx.x * DCH;
    const int h0 = blockIdx.y * HT;
    const int b  = blockIdx.z;
    const float* xg = image + (size_t)b * 2 * VOL;
    const float* rg = xg + VOL;

    for (int i = tid; i < XDL * XHL * 66; i += 256) {
        int wl = i % 66; int rest = i / 66;
        int hl = rest % XHL; int dl = rest / XHL;
        int gw = wl - 1, gh = h0 + hl - 1, gd = d0 + dl - 1;
        float v = 0.0f;
        if (gw >= 0 && gw < Wn && gh >= 0 && gh < Hn && gd >= 0 && gd < Dn)
            v = xg[((size_t)gd * Hn + gh) * Wn + gw];
        xs[(dl * XHL + hl) * XROW + wl] = v;
    }
    __syncthreads();

    const int wt = tid & 15;
    const int ht = tid >> 4;
    const int w0 = wt * 4;

    for (int dl = 0; dl < DCH; dl++) {
        ull P[9][5];
        #pragma unroll
        for (int r9 = 0; r9 < 9; r9++) {
            const int dz = r9 / 3, hy = r9 % 3;
            const float* base = &xs[((dl + dz) * XHL + (ht + hy)) * XROW + w0];
            float4 a  = *(const float4*)base;
            float2 b2 = *(const float2*)(base + 4);
            P[r9][0] = pk2(a.x, a.y);
            P[r9][1] = pk2(a.y, a.z);
            P[r9][2] = pk2(a.z, a.w);
            P[r9][3] = pk2(a.w, b2.x);
            P[r9][4] = pk2(b2.x, b2.y);
        }

        ull z01 = 0ull, z23 = 0ull;

        #pragma unroll 1
        for (int cp = 0; cp < NPAIR; cp++) {
            const ulonglong2* wp = (const ulonglong2*)(ws4 + cp * 28);
            const ulonglong2 bb = ((const ulonglong2*)bp4)[cp];
            ull aA01 = bb.x, aA23 = bb.x;
            ull aB01 = bb.y, aB23 = bb.y;
            #pragma unroll
            for (int t = 0; t < 27; t++) {
                const ulonglong2 w2 = wp[t];       // LDS.128 -> 2 ull pairs
                const int r9 = t / 3, kx = t % 3;
                aA01 = fma2(w2.x, P[r9][kx],     aA01);
                aA23 = fma2(w2.x, P[r9][kx + 2], aA23);
                aB01 = fma2(w2.y, P[r9][kx],     aB01);
                aB23 = fma2(w2.y, P[r9][kx + 2], aB23);
            }
            float a0, a1, a2, a3, b0, b1, b2, b3;
            upk2(aA01, a0, a1); upk2(aA23, a2, a3);
            upk2(aB01, b0, b1); upk2(aB23, b2, b3);
            a0 = fmaxf(a0, 0.f); a1 = fmaxf(a1, 0.f);
            a2 = fmaxf(a2, 0.f); a3 = fmaxf(a3, 0.f);
            b0 = fmaxf(b0, 0.f); b1 = fmaxf(b1, 0.f);
            b2 = fmaxf(b2, 0.f); b3 = fmaxf(b3, 0.f);
            const ulonglong2 pv = ((const ulonglong2*)pp4)[cp];
            z01 = fma2(pv.x, pk2(a0, a1), z01);
            z23 = fma2(pv.x, pk2(a2, a3), z23);
            z01 = fma2(pv.y, pk2(b0, b1), z01);
            z23 = fma2(pv.y, pk2(b2, b3), z23);
        }

        float z0, z1, z2, z3;
        upk2(z01, z0, z1); upk2(z23, z2, z3);

        const int gd = d0 + dl, gh = h0 + ht;
        const size_t o = ((size_t)b * Dn + gd) * PLANE + gh * Wn + w0;
        const float4 r4 = *(const float4*)&rg[((size_t)gd * Hn + gh) * Wn + w0];

        const float p0 = 1.f / (1.f + __expf(-z0));
        const float p1 = 1.f / (1.f + __expf(-z1));
        const float p2 = 1.f / (1.f + __expf(-z2));
        const float p3 = 1.f / (1.f + __expf(-z3));

        *(float4*)&g_p[o]  = make_float4(p0, p1, p2, p3);
        *(float4*)&g_c[o]  = make_float4(r4.x * (1.f - p0), r4.y * (1.f - p1),
                                         r4.z * (1.f - p2), r4.w * (1.f - p3));
        *(float4*)&vout[o] = r4;
    }
}

// ---------------------------------------------------------------------------
// Kernel 2: one propagation iteration.  Block = 32-row half-plane of (b,d).
// Stage 1: d-max (and center stash) -> SMEM.  Stage 2: h-max + w-max via
// shuffles, update, store.  One barrier.  512 blocks, ~6 CTAs/SM.
// ---------------------------------------------------------------------------
__global__ __launch_bounds__(256) void iter_kernel(
    const float4* __restrict__ vin, float4* __restrict__ vout,
    const int* __restrict__ kptr, int it)
{
    __shared__ float4 vz[34 * 16];    // d-max, rows h0-1 .. h0+32 (clamped)
    __shared__ float4 vc[32 * 16];    // center plane stash

    const int blk = blockIdx.x;
    const int bd  = blk >> 1;         // b*64 + d
    const int h0  = (blk & 1) * 32;
    const int d   = bd & 63;
    const int tid = threadIdx.x;
    const bool skip = (it >= *kptr);

    const size_t base = (size_t)bd * 1024;      // plane base in float4 units
    const long long dm = (d > 0)  ? -1024 : 0;
    const long long dp = (d < 63) ?  1024 : 0;

    // Stage 1: d-max for 34 rows x 16 float4; stash center for interior rows
    #pragma unroll
    for (int q = 0; q < 3; q++) {
        const int i = tid + q * 256;
        if (i < 34 * 16) {
            const int row = i >> 4, c4 = i & 15;
            int gh = h0 + row - 1;
            gh = max(0, min(63, gh));
            const size_t off = base + gh * 16 + c4;
            const float4 cen = vin[off];
            float4 m = max4(cen, vin[off + dm]);
            m = max4(m, vin[off + dp]);
            vz[i] = m;
            if (row >= 1 && row <= 32) vc[i - 16] = cen;
        }
    }
    __syncthreads();

    // Stage 2: h-max + w-max + update (2 tasks/thread)
    #pragma unroll
    for (int q = 0; q < 2; q++) {
        const int i  = tid + q * 256;
        const int ro = i >> 4;        // 0..31
        const int c4 = i & 15;        // 0..15

        float4 hm = max4(max4(vz[ro * 16 + c4], vz[(ro + 1) * 16 + c4]),
                         vz[(ro + 2) * 16 + c4]);

        float lf = __shfl_up_sync(0xffffffffu, hm.w, 1);
        float rt = __shfl_down_sync(0xffffffffu, hm.x, 1);
        if (c4 == 0)  lf = hm.x;      // w==0 edge (also fixes row crossing)
        if (c4 == 15) rt = hm.w;      // w==63 edge

        float4 m;
        m.x = fmaxf(lf,   fmaxf(hm.x, hm.y));
        m.y = fmaxf(hm.x, fmaxf(hm.y, hm.z));
        m.z = fmaxf(hm.y, fmaxf(hm.z, hm.w));
        m.w = fmaxf(hm.z, fmaxf(hm.w, rt));

        const size_t off = base + (h0 + ro) * 16 + c4;
        const float4 cen = vc[ro * 16 + c4];
        const float4 pp  = ((const float4*)g_p)[off];
        const float4 cc  = ((const float4*)g_c)[off];

        float4 nv;
        nv.x = fmaxf(cen.x, fmaf(pp.x, m.x, cc.x));
        nv.y = fmaxf(cen.y, fmaf(pp.y, m.y, cc.y));
        nv.z = fmaxf(cen.z, fmaf(pp.z, m.z, cc.z));
        nv.w = fmaxf(cen.w, fmaf(pp.w, m.w, cc.w));

        vout[off] = skip ? cen : nv;
    }
}

// ---------------------------------------------------------------------------
extern "C" void kernel_launch(void* const* d_in, const int* in_sizes, int n_in,
                              void* d_out, int out_size)
{
    const float* image = (const float*)d_in[0];
    const float* hw    = (const float*)d_in[1];
    const float* hb    = (const float*)d_in[2];
    const float* pw    = (const float*)d_in[3];
    const int*   kptr  = (const int*)d_in[4];
    float* out = (float*)d_out;

    void* pv = nullptr;
    cudaGetSymbolAddress(&pv, g_v);
    float* vbuf = (float*)pv;

    compute_p_kernel<<<dim3(16, 4, 4), 256>>>(image, hw, hb, pw, out);

    const float* src = out;
    float* dst = vbuf;
    for (int i = 0; i < 30; i++) {
        iter_kernel<<<Bn * Dn * 2, 256>>>((const float4*)src, (float4*)dst, kptr, i);
        float* t = dst; dst = (float*)src; src = t;
    }
    // 30 iterations (even count): final write lands in d_out.
}